// round 3
// baseline (speedup 1.0000x reference)
#include <cuda_runtime.h>
#include <math.h>

// ============================================================================
// Encoder_multi: 2-layer bidirectional "LSTM" from zero state == 4 fused GEMMs.
//   B=32, T=256, E=512, H=512, M=B*T=8192.
//   Gate order i,f,g,o; f-gate and W_hh are dead (h0=c0=0).
//   Effective: gates needed = {i,g,o} -> N = 2 dirs * 3 gates * 512 h = 3072.
//
// Outputs (float32, concatenated): h_last (2,32,512) | c_last (2,32,512) |
//   encoder_out (32,256,2,512).
// ============================================================================

#define MT   64          // M tile
#define NHT  32          // h-columns per tile (N tile = NHT*6 = 192)
#define NT   192
#define KT   32          // K tile
#define APAD 36          // A smem row stride (floats)
#define BPAD 196         // B smem row stride (floats)

#define M_TOTAL 8192
#define OUT_H   0
#define OUT_C   32768        // 2*32*512
#define OUT_ENC 65536        // 2*(2*32*512)

// Inter-layer activations: inp1 = concat(h0f, h0b) : (8192, 1024)
__device__ float g_inp1[M_TOTAL * 1024];

__device__ __forceinline__ float sigmoidf_(float x) {
    return 1.0f / (1.0f + expf(-x));
}

// LAYER: 0 (A = emb[x], K=512) or 1 (A = g_inp1, K=1024).
// W: (2, 2048, K) row-major flattened -> row = dir*2048 + gate_off + h.
template<int LAYER, int K>
__global__ __launch_bounds__(256, 2)
void lstm_gemm(const int* __restrict__ x,
               const float* __restrict__ emb,
               const float* __restrict__ W,
               const float* __restrict__ b_ih,
               const float* __restrict__ b_hh,
               float* __restrict__ out)
{
    __shared__ float sA[MT * APAD];       // [r][k], r = M row in tile
    __shared__ float sB[KT * BPAD];       // [k][n], n = h_local*6 + dir*3 + gate
    __shared__ int   sx[MT];

    const int tid = threadIdx.x;
    const int tx  = tid & 31;             // h column within tile (0..31)
    const int ty  = tid >> 5;             // warp id = row group (0..7)
    const int m0  = blockIdx.x * MT;      // 128 blocks
    const int h0  = blockIdx.y * NHT;     // 16 blocks
    const int h   = h0 + tx;

    if (LAYER == 0) {
        if (tid < MT) sx[tid] = x[m0 + tid];
        __syncthreads();
    }

    float acc[8][6];
    #pragma unroll
    for (int i = 0; i < 8; ++i)
        #pragma unroll
        for (int j = 0; j < 6; ++j) acc[i][j] = 0.0f;

    const int lr  = tid >> 3;   // 0..31 : row within load pass
    const int lc4 = tid & 7;    // 0..7  : float4 column within K tile

    for (int kb = 0; kb < K; kb += KT) {
        // ---- A tile: 64 rows x 32 k, 2 passes of float4 per thread ----
        #pragma unroll
        for (int p = 0; p < 2; ++p) {
            const int r = lr + p * 32;
            const float* arow;
            if (LAYER == 0) arow = emb + (size_t)sx[r] * 512;
            else            arow = g_inp1 + (size_t)(m0 + r) * 1024;
            float4 v = *(const float4*)(arow + kb + lc4 * 4);
            *(float4*)(&sA[r * APAD + lc4 * 4]) = v;
        }
        // ---- B tile: 192 n x 32 k, transposed into smem [k][n] ----
        #pragma unroll
        for (int p = 0; p < 6; ++p) {
            const int n   = p * 32 + lr;
            const int hl  = n / 6;
            const int rem = n - hl * 6;
            const int dir = (rem >= 3) ? 1 : 0;
            const int g   = rem - dir * 3;
            const int goff = (g == 0) ? 0 : ((g == 1) ? 1024 : 1536);
            const int wrow = dir * 2048 + goff + h0 + hl;
            float4 v = *(const float4*)(W + (size_t)wrow * K + kb + lc4 * 4);
            const int kk = lc4 * 4;
            sB[(kk + 0) * BPAD + n] = v.x;
            sB[(kk + 1) * BPAD + n] = v.y;
            sB[(kk + 2) * BPAD + n] = v.z;
            sB[(kk + 3) * BPAD + n] = v.w;
        }
        __syncthreads();

        // ---- inner product: each thread 8 rows x 6 gate-cols of one h ----
        #pragma unroll
        for (int kk = 0; kk < KT; ++kk) {
            float a[8];
            #pragma unroll
            for (int i = 0; i < 8; ++i)
                a[i] = sA[(ty * 8 + i) * APAD + kk];
            const float* bp = &sB[kk * BPAD + tx * 6];
            float2 b01 = *(const float2*)(bp + 0);
            float2 b23 = *(const float2*)(bp + 2);
            float2 b45 = *(const float2*)(bp + 4);
            float b[6] = { b01.x, b01.y, b23.x, b23.y, b45.x, b45.y };
            #pragma unroll
            for (int i = 0; i < 8; ++i) {
                #pragma unroll
                for (int j = 0; j < 6; ++j)
                    acc[i][j] = fmaf(a[i], b[j], acc[i][j]);
            }
        }
        __syncthreads();
    }

    // ---- fused epilogue: bias + LSTM-cell pointwise + scatter ----
    float bias[6];
    #pragma unroll
    for (int d = 0; d < 2; ++d)
        #pragma unroll
        for (int g = 0; g < 3; ++g) {
            const int goff = (g == 0) ? 0 : ((g == 1) ? 1024 : 1536);
            const int wrow = d * 2048 + goff + h;
            bias[d * 3 + g] = b_ih[wrow] + b_hh[wrow];
        }

    #pragma unroll
    for (int rr = 0; rr < 8; ++rr) {
        const int m = m0 + ty * 8 + rr;
        const float i_f = acc[rr][0] + bias[0];
        const float g_f = acc[rr][1] + bias[1];
        const float o_f = acc[rr][2] + bias[2];
        const float c_f = sigmoidf_(i_f) * tanhf(g_f);
        const float h_f = sigmoidf_(o_f) * tanhf(c_f);
        const float i_b = acc[rr][3] + bias[3];
        const float g_b = acc[rr][4] + bias[4];
        const float o_b = acc[rr][5] + bias[5];
        const float c_b = sigmoidf_(i_b) * tanhf(g_b);
        const float h_b = sigmoidf_(o_b) * tanhf(c_b);

        // encoder_out[b][t][LAYER][h] = h_f + h_b
        out[OUT_ENC + (size_t)(m * 2 + LAYER) * 512 + h] = h_f + h_b;

        if (LAYER == 0) {
            g_inp1[(size_t)m * 1024 + h]       = h_f;
            g_inp1[(size_t)m * 1024 + 512 + h] = h_b;
        }
        if ((m & 255) == 255) {              // t == T-1: h_last / c_last (fwd dir)
            const int bb = m >> 8;
            out[OUT_H + LAYER * 16384 + bb * 512 + h] = h_f;
            out[OUT_C + LAYER * 16384 + bb * 512 + h] = c_f;
        }
    }
}

extern "C" void kernel_launch(void* const* d_in, const int* in_sizes, int n_in,
                              void* d_out, int out_size)
{
    const int*   x    = (const int*)  d_in[0];
    const float* emb  = (const float*)d_in[1];
    const float* W0   = (const float*)d_in[2];   // (2, 2048, 512)
    // d_in[3] = W_hh_l0 : dead (h0 = 0)
    const float* bih0 = (const float*)d_in[4];
    const float* bhh0 = (const float*)d_in[5];
    const float* W1   = (const float*)d_in[6];   // (2, 2048, 1024)
    // d_in[7] = W_hh_l1 : dead
    const float* bih1 = (const float*)d_in[8];
    const float* bhh1 = (const float*)d_in[9];
    float* out = (float*)d_out;

    dim3 grid(M_TOTAL / MT, 3072 / NT);   // (128, 16)
    dim3 block(256);
    lstm_gemm<0,  512><<<grid, block>>>(x, emb, W0, bih0, bhh0, out);
    lstm_gemm<1, 1024><<<grid, block>>>(x, emb, W1, bih1, bhh1, out);
}

// round 4
// speedup vs baseline: 1.3694x; 1.3694x over previous
#include <cuda_runtime.h>
#include <math.h>

// ============================================================================
// Encoder_multi via tf32 tensor cores (mma.sync.m16n8k8) with 3xTF32 split.
//   C[8192, 3072] = A[8192,K] * W_sel[3072,K]^T  for layer 0 (K=512), 1 (K=1024)
//   n packing: n = h*6 + dir*3 + gate(i,g,o)  -> fused LSTM-cell epilogue.
// Block: BM=128, BN=96 (16 h), KT=32. 8 warps (4m x 2n), warp tile 32x48.
// Split: v = hi + lo (both tf32);  C = hi*hi + hi*lo + lo*hi  (err ~1e-6).
// ============================================================================

#define M_TOTAL 8192
#define OUT_C   32768
#define OUT_ENC 65536

// smem float offsets within one K-tile buffer (pad-36 rows)
#define A_HI 0              // [128][36]
#define A_LO 4608
#define B_HI 9216           // [96][36]
#define B_LO 12672
#define BUF  16128          // floats per buffer
#define SMEM_BYTES (2 * BUF * 4)   // 129024 B

__device__ float g_inp1[M_TOTAL * 1024];

__device__ __forceinline__ float sigmoidf_(float x) { return 1.0f / (1.0f + expf(-x)); }

__device__ __forceinline__ float tf32_rna(float f) {
    unsigned u;
    asm("cvt.rna.tf32.f32 %0, %1;" : "=r"(u) : "f"(f));
    return __uint_as_float(u);
}

__device__ __forceinline__ void mma8(float c[4], const unsigned a[4], const unsigned b[2]) {
    asm volatile(
        "mma.sync.aligned.m16n8k8.row.col.f32.tf32.tf32.f32 "
        "{%0,%1,%2,%3}, {%4,%5,%6,%7}, {%8,%9}, {%0,%1,%2,%3};"
        : "+f"(c[0]), "+f"(c[1]), "+f"(c[2]), "+f"(c[3])
        : "r"(a[0]), "r"(a[1]), "r"(a[2]), "r"(a[3]), "r"(b[0]), "r"(b[1]));
}

template<int LAYER, int K>
__global__ __launch_bounds__(256, 1)
void lstm_mma(const int* __restrict__ x, const float* __restrict__ emb,
              const float* __restrict__ W, const float* __restrict__ b_ih,
              const float* __restrict__ b_hh, float* __restrict__ out)
{
    extern __shared__ float sm[];
    __shared__ int   sx[128];
    __shared__ float sBias[96];

    const int tid = threadIdx.x;
    const int m0  = blockIdx.x * 128;
    const int h0  = blockIdx.y * 16;

    if (LAYER == 0 && tid < 128) sx[tid] = x[m0 + tid];
    if (tid < 96) {
        int hl = tid / 6, rem = tid - hl * 6;
        int dir = (rem >= 3) ? 1 : 0, g = rem - dir * 3;
        int goff = (g == 0) ? 0 : ((g == 1) ? 1024 : 1536);
        int wrow = dir * 2048 + goff + h0 + hl;
        sBias[tid] = b_ih[wrow] + b_hh[wrow];
    }
    __syncthreads();

    // ---- producer setup (gmem row pointers hoisted out of the K loop) ----
    const int lr = tid >> 3;            // 0..31
    const int k4 = (tid & 7) * 4;       // 0,4,...,28
    const float* aptr[4];
    #pragma unroll
    for (int p = 0; p < 4; ++p) {
        int r = lr + p * 32;
        aptr[p] = (LAYER == 0) ? (emb + (size_t)sx[r] * 512)
                               : (g_inp1 + (size_t)(m0 + r) * 1024);
    }
    const float* bptr[3];
    #pragma unroll
    for (int p = 0; p < 3; ++p) {
        int n = lr + p * 32;
        int hl = n / 6, rem = n - hl * 6;
        int dir = (rem >= 3) ? 1 : 0, g = rem - dir * 3;
        int goff = (g == 0) ? 0 : ((g == 1) ? 1024 : 1536);
        int wrow = dir * 2048 + goff + h0 + hl;
        bptr[p] = W + (size_t)wrow * K;
    }

    // ---- consumer setup ----
    const int warp = tid >> 5, lane = tid & 31;
    const int wm = warp >> 1, wn = warp & 1;
    const int gq = lane >> 2, tg = lane & 3;   // groupID, threadID_in_group
    const int mb = wm * 32, nb = wn * 48;

    float acc[2][6][4];
    #pragma unroll
    for (int mt = 0; mt < 2; ++mt)
        #pragma unroll
        for (int nt = 0; nt < 6; ++nt)
            #pragma unroll
            for (int j = 0; j < 4; ++j) acc[mt][nt][j] = 0.0f;

    constexpr int NITER = K / 32;
    float4 ra[4], rb[3];

    // prologue: load + split + store tile 0
    #pragma unroll
    for (int p = 0; p < 4; ++p) ra[p] = *(const float4*)(aptr[p] + k4);
    #pragma unroll
    for (int p = 0; p < 3; ++p) rb[p] = *(const float4*)(bptr[p] + k4);
    {
        float* buf = sm;
        #pragma unroll
        for (int p = 0; p < 4; ++p) {
            int r = lr + p * 32;
            float4 hi, lo;
            hi.x = tf32_rna(ra[p].x); lo.x = tf32_rna(ra[p].x - hi.x);
            hi.y = tf32_rna(ra[p].y); lo.y = tf32_rna(ra[p].y - hi.y);
            hi.z = tf32_rna(ra[p].z); lo.z = tf32_rna(ra[p].z - hi.z);
            hi.w = tf32_rna(ra[p].w); lo.w = tf32_rna(ra[p].w - hi.w);
            *(float4*)(buf + A_HI + r * 36 + k4) = hi;
            *(float4*)(buf + A_LO + r * 36 + k4) = lo;
        }
        #pragma unroll
        for (int p = 0; p < 3; ++p) {
            int n = lr + p * 32;
            float4 hi, lo;
            hi.x = tf32_rna(rb[p].x); lo.x = tf32_rna(rb[p].x - hi.x);
            hi.y = tf32_rna(rb[p].y); lo.y = tf32_rna(rb[p].y - hi.y);
            hi.z = tf32_rna(rb[p].z); lo.z = tf32_rna(rb[p].z - hi.z);
            hi.w = tf32_rna(rb[p].w); lo.w = tf32_rna(rb[p].w - hi.w);
            *(float4*)(buf + B_HI + n * 36 + k4) = hi;
            *(float4*)(buf + B_LO + n * 36 + k4) = lo;
        }
    }
    __syncthreads();

    for (int it = 0; it < NITER; ++it) {
        // prefetch next tile into registers (LDG latency covered by mma)
        if (it + 1 < NITER) {
            const int kb = (it + 1) * 32;
            #pragma unroll
            for (int p = 0; p < 4; ++p) ra[p] = *(const float4*)(aptr[p] + kb + k4);
            #pragma unroll
            for (int p = 0; p < 3; ++p) rb[p] = *(const float4*)(bptr[p] + kb + k4);
        }

        const float* buf = sm + (it & 1) * BUF;
        #pragma unroll
        for (int ks = 0; ks < 4; ++ks) {
            unsigned a1[2][4], a2[2][4];
            #pragma unroll
            for (int mt = 0; mt < 2; ++mt)
                #pragma unroll
                for (int s = 0; s < 4; ++s) {
                    int r = mb + mt * 16 + gq + (s & 1) * 8;
                    int c = ks * 8 + tg + (s >> 1) * 4;
                    a1[mt][s] = __float_as_uint(buf[A_HI + r * 36 + c]);
                    a2[mt][s] = __float_as_uint(buf[A_LO + r * 36 + c]);
                }
            unsigned b1[6][2], b2[6][2];
            #pragma unroll
            for (int nt = 0; nt < 6; ++nt)
                #pragma unroll
                for (int s = 0; s < 2; ++s) {
                    int kk = ks * 8 + tg + s * 4;
                    int n  = nb + nt * 8 + gq;
                    b1[nt][s] = __float_as_uint(buf[B_HI + n * 36 + kk]);
                    b2[nt][s] = __float_as_uint(buf[B_LO + n * 36 + kk]);
                }
            #pragma unroll
            for (int mt = 0; mt < 2; ++mt)
                #pragma unroll
                for (int nt = 0; nt < 6; ++nt) {
                    mma8(acc[mt][nt], a1[mt], b1[nt]);   // hi*hi
                    mma8(acc[mt][nt], a1[mt], b2[nt]);   // hi*lo
                    mma8(acc[mt][nt], a2[mt], b1[nt]);   // lo*hi
                }
        }

        // split + store next tile into the other buffer
        if (it + 1 < NITER) {
            float* nbuf = sm + ((it + 1) & 1) * BUF;
            #pragma unroll
            for (int p = 0; p < 4; ++p) {
                int r = lr + p * 32;
                float4 hi, lo;
                hi.x = tf32_rna(ra[p].x); lo.x = tf32_rna(ra[p].x - hi.x);
                hi.y = tf32_rna(ra[p].y); lo.y = tf32_rna(ra[p].y - hi.y);
                hi.z = tf32_rna(ra[p].z); lo.z = tf32_rna(ra[p].z - hi.z);
                hi.w = tf32_rna(ra[p].w); lo.w = tf32_rna(ra[p].w - hi.w);
                *(float4*)(nbuf + A_HI + r * 36 + k4) = hi;
                *(float4*)(nbuf + A_LO + r * 36 + k4) = lo;
            }
            #pragma unroll
            for (int p = 0; p < 3; ++p) {
                int n = lr + p * 32;
                float4 hi, lo;
                hi.x = tf32_rna(rb[p].x); lo.x = tf32_rna(rb[p].x - hi.x);
                hi.y = tf32_rna(rb[p].y); lo.y = tf32_rna(rb[p].y - hi.y);
                hi.z = tf32_rna(rb[p].z); lo.z = tf32_rna(rb[p].z - hi.z);
                hi.w = tf32_rna(rb[p].w); lo.w = tf32_rna(rb[p].w - hi.w);
                *(float4*)(nbuf + B_HI + n * 36 + k4) = hi;
                *(float4*)(nbuf + B_LO + n * 36 + k4) = lo;
            }
        }
        __syncthreads();
    }

    // ---- epilogue: accums -> smem C tile [128][100] -> fused LSTM cell ----
    float* sC = sm;
    #pragma unroll
    for (int mt = 0; mt < 2; ++mt)
        #pragma unroll
        for (int nt = 0; nt < 6; ++nt) {
            int r0 = mb + mt * 16 + gq;
            int c0 = nb + nt * 8 + tg * 2;
            *(float2*)(sC + r0 * 100 + c0)       = make_float2(acc[mt][nt][0], acc[mt][nt][1]);
            *(float2*)(sC + (r0 + 8) * 100 + c0) = make_float2(acc[mt][nt][2], acc[mt][nt][3]);
        }
    __syncthreads();

    #pragma unroll
    for (int p = 0; p < 8; ++p) {
        int idx = tid + p * 256;          // 2048 (m,h) pairs
        int ml = idx >> 4, hl = idx & 15;
        const float* cp = sC + ml * 100 + hl * 6;
        const float* bp = sBias + hl * 6;

        float i_f = cp[0] + bp[0], g_f = cp[1] + bp[1], o_f = cp[2] + bp[2];
        float c_f = sigmoidf_(i_f) * tanhf(g_f);
        float h_f = sigmoidf_(o_f) * tanhf(c_f);
        float i_b = cp[3] + bp[3], g_b = cp[4] + bp[4], o_b = cp[5] + bp[5];
        float c_b = sigmoidf_(i_b) * tanhf(g_b);
        float h_b = sigmoidf_(o_b) * tanhf(c_b);

        int m = m0 + ml, h = h0 + hl;
        out[OUT_ENC + (size_t)(m * 2 + LAYER) * 512 + h] = h_f + h_b;
        if (LAYER == 0) {
            g_inp1[(size_t)m * 1024 + h]       = h_f;
            g_inp1[(size_t)m * 1024 + 512 + h] = h_b;
        }
        if ((m & 255) == 255) {
            int bb = m >> 8;
            out[LAYER * 16384 + bb * 512 + h]         = h_f;   // h_last
            out[OUT_C + LAYER * 16384 + bb * 512 + h] = c_f;   // c_last
        }
    }
}

extern "C" void kernel_launch(void* const* d_in, const int* in_sizes, int n_in,
                              void* d_out, int out_size)
{
    const int*   x    = (const int*)  d_in[0];
    const float* emb  = (const float*)d_in[1];
    const float* W0   = (const float*)d_in[2];   // (2, 2048, 512)
    const float* bih0 = (const float*)d_in[4];
    const float* bhh0 = (const float*)d_in[5];
    const float* W1   = (const float*)d_in[6];   // (2, 2048, 1024)
    const float* bih1 = (const float*)d_in[8];
    const float* bhh1 = (const float*)d_in[9];
    float* out = (float*)d_out;

    cudaFuncSetAttribute(lstm_mma<0, 512>,
                         cudaFuncAttributeMaxDynamicSharedMemorySize, SMEM_BYTES);
    cudaFuncSetAttribute(lstm_mma<1, 1024>,
                         cudaFuncAttributeMaxDynamicSharedMemorySize, SMEM_BYTES);

    dim3 grid(M_TOTAL / 128, 512 / 16);   // (64, 32)
    dim3 block(256);
    lstm_mma<0, 512><<<grid, block, SMEM_BYTES>>>(x, emb, W0, bih0, bhh0, out);
    lstm_mma<1, 1024><<<grid, block, SMEM_BYTES>>>(x, emb, W1, bih1, bhh1, out);
}